// round 1
// baseline (speedup 1.0000x reference)
#include <cuda_runtime.h>
#include <math_constants.h>

// YOLOV3TargetMerger: b=32, N=22743, M=50, C=80
// Inputs (metadata order):
//   0 box_preds [b,N,4] f32
//   1 gt_boxes  [b,M,4] f32
//   2 obj_t     [b,N,1] f32
//   3 centers_t [b,N,2] f32
//   4 scales_t  [b,N,2] f32
//   5 weights_t [b,N,2] f32
//   6 clas_t    [b,N,C] f32
// Output (concatenated, f32):
//   objectness [S], centers [2S], scales [2S], weights [2S],
//   class_targets [80S], class_mask [80S]   (S = b*N, total 167S)

#define BATCH 32
#define MGT   50
#define NCLS  80
#define IGNORE_THR 0.7f

__global__ void merge_main_kernel(const float4* __restrict__ bp,
                                  const float4* __restrict__ gt,
                                  const float*  __restrict__ obj,
                                  const float2* __restrict__ cen,
                                  const float2* __restrict__ sca,
                                  const float2* __restrict__ wei,
                                  float* __restrict__ out,
                                  int N, long long S)
{
    __shared__ float4 sgt[MGT];
    const int b = blockIdx.y;
    if (threadIdx.x < MGT) sgt[threadIdx.x] = gt[b * MGT + threadIdx.x];
    __syncthreads();

    const int n = blockIdx.x * blockDim.x + threadIdx.x;
    if (n >= N) return;
    const long long i = (long long)b * N + n;

    const float4 p = bp[i];
    const float area_p = (p.z - p.x) * (p.w - p.y);

    float best = -CUDART_INF_F;
#pragma unroll 10
    for (int m = 0; m < MGT; m++) {
        const float4 g = sgt[m];
        const float tlx = fmaxf(p.x, g.x);
        const float tly = fmaxf(p.y, g.y);
        const float brx = fminf(p.z, g.z);
        const float bry = fminf(p.w, g.w);
        const float w = fmaxf(brx - tlx, 0.0f);
        const float h = fmaxf(bry - tly, 0.0f);
        const float inter = w * h;
        const float area_g = (g.z - g.x) * (g.w - g.y);
        const float uni = area_p + area_g - inter;
        const float iou = inter / (uni + 1e-12f);
        best = fmaxf(best, iou);
    }

    const float dyn  = (best > IGNORE_THR) ? -1.0f : 0.0f;
    const float o    = obj[i];
    const bool  mask = (o > 0.0f);

    // objectness
    out[i] = mask ? o : dyn;

    const float2 z = make_float2(0.0f, 0.0f);
    const float2 c = cen[i];
    const float2 s = sca[i];
    const float2 w = wei[i];
    ((float2*)(out + S       ))[i] = mask ? c : z;
    ((float2*)(out + 3 * S   ))[i] = mask ? s : z;
    ((float2*)(out + 5 * S   ))[i] = mask ? w : z;
}

__global__ void merge_class_kernel(const float*  __restrict__ obj,
                                   const float4* __restrict__ cls,
                                   float4* __restrict__ out_t,
                                   float4* __restrict__ out_m,
                                   long long total4)   // = S * NCLS/4
{
    const long long idx = (long long)blockIdx.x * blockDim.x + threadIdx.x;
    if (idx >= total4) return;

    const long long anchor = idx / (NCLS / 4);
    const bool mask = (obj[anchor] > 0.0f);

    const float4 c = cls[idx];
    float4 t, m;
    t.x = mask ? c.x : -1.0f;  m.x = (mask && t.x >= 0.0f) ? 1.0f : 0.0f;
    t.y = mask ? c.y : -1.0f;  m.y = (mask && t.y >= 0.0f) ? 1.0f : 0.0f;
    t.z = mask ? c.z : -1.0f;  m.z = (mask && t.z >= 0.0f) ? 1.0f : 0.0f;
    t.w = mask ? c.w : -1.0f;  m.w = (mask && t.w >= 0.0f) ? 1.0f : 0.0f;

    out_t[idx] = t;
    out_m[idx] = m;
}

extern "C" void kernel_launch(void* const* d_in, const int* in_sizes, int n_in,
                              void* d_out, int out_size)
{
    const float4* bp  = (const float4*)d_in[0];
    const float4* gt  = (const float4*)d_in[1];
    const float*  obj = (const float*) d_in[2];
    const float2* cen = (const float2*)d_in[3];
    const float2* sca = (const float2*)d_in[4];
    const float2* wei = (const float2*)d_in[5];
    const float*  cls = (const float*) d_in[6];

    const long long S = in_sizes[2];          // b * N
    const int N = (int)(S / BATCH);
    float* out = (float*)d_out;

    // Kernel A: objectness + centers/scales/weights (7 floats per anchor)
    {
        dim3 block(256, 1, 1);
        dim3 grid((N + 255) / 256, BATCH, 1);
        merge_main_kernel<<<grid, block>>>(bp, gt, obj, cen, sca, wei, out, N, S);
    }

    // Kernel B: class_targets + class_mask (float4-vectorized over C=80)
    {
        const long long total4 = S * (NCLS / 4);
        float4* out_t = (float4*)(out + 7LL * S);
        float4* out_m = (float4*)(out + 87LL * S);
        const int threads = 256;
        const long long blocks = (total4 + threads - 1) / threads;
        merge_class_kernel<<<(unsigned)blocks, threads>>>(obj, (const float4*)cls,
                                                          out_t, out_m, total4);
    }
}

// round 3
// speedup vs baseline: 1.3374x; 1.3374x over previous
#include <cuda_runtime.h>

// YOLOV3TargetMerger: b=32, N=22743, M=50, C=80
// Inputs: 0 box_preds[b,N,4] 1 gt_boxes[b,M,4] 2 obj_t[b,N,1]
//         3 centers_t[b,N,2] 4 scales_t[b,N,2] 5 weights_t[b,N,2] 6 clas_t[b,N,80]
// Output (concat f32): obj[S], cen[2S], sca[2S], wei[2S], cls_t[80S], cls_m[80S]

#define BATCH 32
#define MGT   50
#define NCLS  80
#define C4    (NCLS / 4)
#define AB    256          // anchors per block
#define THR   0.7f
#define EPSF  1e-12f

__global__ void __launch_bounds__(AB) fused_merge_kernel(
    const float4* __restrict__ bp,
    const float4* __restrict__ gt,
    const float*  __restrict__ obj,
    const float2* __restrict__ cen,
    const float2* __restrict__ sca,
    const float2* __restrict__ wei,
    const float4* __restrict__ cls4,
    float* __restrict__ out,
    int N, long long S)
{
    __shared__ float4 sgt[MGT];
    __shared__ float  sarea[MGT];
    __shared__ unsigned char smask[AB];

    const int b  = blockIdx.y;
    const int a0 = blockIdx.x * AB;
    const int t  = threadIdx.x;

    if (t < MGT) {
        const float4 g = gt[b * MGT + t];
        sgt[t]   = g;
        sarea[t] = (g.z - g.x) * (g.w - g.y);
    }
    __syncthreads();

    const int nA = min(AB, N - a0);

    // ---------------- phase 1: IOU hit + obj/cen/sca/wei ----------------
    if (t < nA) {
        const long long i = (long long)b * N + (a0 + t);
        const float4 p = bp[i];
        const float area_p = (p.z - p.x) * (p.w - p.y);

        bool hit = false, ambig = false;
#pragma unroll 10
        for (int m = 0; m < MGT; m++) {
            const float4 g = sgt[m];
            const float w = fmaxf(fminf(p.z, g.z) - fmaxf(p.x, g.x), 0.0f);
            const float h = fmaxf(fminf(p.w, g.w) - fmaxf(p.y, g.y), 0.0f);
            const float inter = w * h;
            float u = area_p + sarea[m];
            u = u - inter;
            const float d = u + EPSF;            // ref denominator, same op order
            const float thr  = THR * d;
            const float diff = inter - thr;
            const float marg = 1e-6f * thr;
            const bool pos = (d > 0.0f);
            hit   = hit   | (pos & (diff >  marg));
            ambig = ambig | (pos & (fabsf(diff) <= marg));
        }
        if (ambig) {                              // rare: redo exactly (IEEE div)
            hit = false;
            for (int m = 0; m < MGT; m++) {
                const float4 g = sgt[m];
                const float w = fmaxf(fminf(p.z, g.z) - fmaxf(p.x, g.x), 0.0f);
                const float h = fmaxf(fminf(p.w, g.w) - fmaxf(p.y, g.y), 0.0f);
                const float inter = w * h;
                float u = area_p + sarea[m];
                u = u - inter;
                const float d = u + EPSF;
                hit = hit | ((inter / d) > THR);  // d<0 -> iou<=0 -> false, matches ref
            }
        }

        const float o    = obj[i];
        const bool  mask = (o > 0.0f);
        smask[t] = mask;

        out[i] = mask ? o : (hit ? -1.0f : 0.0f);

        const float2 z = make_float2(0.0f, 0.0f);
        const float2 c = cen[i];
        const float2 s = sca[i];
        const float2 w = wei[i];
        ((float2*)(out + S     ))[i] = mask ? c : z;
        ((float2*)(out + 3 * S ))[i] = mask ? s : z;
        ((float2*)(out + 5 * S ))[i] = mask ? w : z;
    }
    __syncthreads();

    // ---------------- phase 2: class targets + mask (coalesced f4) -------
    const long long base = ((long long)b * N + a0) * C4;
    const float4* cb = cls4 + base;
    float4* tb = (float4*)(out + 7LL  * S) + base;
    float4* mb = (float4*)(out + 87LL * S) + base;

    const int tot = nA * C4;
    for (int idx = t; idx < tot; idx += AB) {
        const bool mask = smask[idx / C4];
        const float4 c = __ldcs(cb + idx);
        float4 tv, mv;
        tv.x = mask ? c.x : -1.0f;  mv.x = (mask & (c.x >= 0.0f)) ? 1.0f : 0.0f;
        tv.y = mask ? c.y : -1.0f;  mv.y = (mask & (c.y >= 0.0f)) ? 1.0f : 0.0f;
        tv.z = mask ? c.z : -1.0f;  mv.z = (mask & (c.z >= 0.0f)) ? 1.0f : 0.0f;
        tv.w = mask ? c.w : -1.0f;  mv.w = (mask & (c.w >= 0.0f)) ? 1.0f : 0.0f;
        __stcs(tb + idx, tv);
        __stcs(mb + idx, mv);
    }
}

extern "C" void kernel_launch(void* const* d_in, const int* in_sizes, int n_in,
                              void* d_out, int out_size)
{
    const float4* bp  = (const float4*)d_in[0];
    const float4* gt  = (const float4*)d_in[1];
    const float*  obj = (const float*) d_in[2];
    const float2* cen = (const float2*)d_in[3];
    const float2* sca = (const float2*)d_in[4];
    const float2* wei = (const float2*)d_in[5];
    const float4* cls = (const float4*)d_in[6];

    const long long S = in_sizes[2];      // b * N
    const int N = (int)(S / BATCH);
    float* out = (float*)d_out;

    dim3 block(AB, 1, 1);
    dim3 grid((N + AB - 1) / AB, BATCH, 1);
    fused_merge_kernel<<<grid, block>>>(bp, gt, obj, cen, sca, wei, cls, out, N, S);
}

// round 4
// speedup vs baseline: 1.3636x; 1.0195x over previous
#include <cuda_runtime.h>

// YOLOV3TargetMerger: b=32, N=22743, M=50, C=80
// Inputs: 0 box_preds[b,N,4] 1 gt_boxes[b,M,4] 2 obj_t[b,N,1]
//         3 centers_t[b,N,2] 4 scales_t[b,N,2] 5 weights_t[b,N,2] 6 clas_t[b,N,80]
// Output (concat f32): obj[S], cen[2S], sca[2S], wei[2S], cls_t[80S], cls_m[80S]

#define BATCH 32
#define MGT   50
#define NCLS  80
#define C4    (NCLS / 4)
#define AB    256          // anchors per block
#define THR   0.7f
#define EPSF  1e-12f

__global__ void __launch_bounds__(AB) fused_merge_kernel(
    const float4* __restrict__ bp,
    const float4* __restrict__ gt,
    const float*  __restrict__ obj,
    const float2* __restrict__ cen,
    const float2* __restrict__ sca,
    const float2* __restrict__ wei,
    const float4* __restrict__ cls4,
    float* __restrict__ out,
    int N, long long S)
{
    __shared__ float4 sgt[MGT];
    __shared__ float  sarea[MGT];
    __shared__ unsigned char smask[AB];
    __shared__ int    scnt;

    const int b  = blockIdx.y;
    const int a0 = blockIdx.x * AB;
    const int t  = threadIdx.x;

    // ---- compact gt boxes: any gt with non-positive width/height has
    // inter == 0 vs EVERY anchor, and inter==0 can never trigger a hit
    // (hit needs d>0 and then 0 > 0.7*d is false; also outside the band).
    if (t == 0) scnt = 0;
    __syncthreads();
    if (t < MGT) {
        const float4 g = gt[b * MGT + t];
        if (g.z > g.x && g.w > g.y) {
            const int k = atomicAdd(&scnt, 1);
            sgt[k]   = g;
            sarea[k] = (g.z - g.x) * (g.w - g.y);
        }
    }
    __syncthreads();
    const int K = scnt;                   // expected ~12.5 of 50

    const int nA = min(AB, N - a0);

    // ---------------- phase 1: IOU hit + obj/cen/sca/wei ----------------
    if (t < nA) {
        const long long i = (long long)b * N + (a0 + t);
        const float4 p = bp[i];
        const float area_p = (p.z - p.x) * (p.w - p.y);

        bool hit = false, ambig = false;
        for (int m = 0; m < K; m++) {
            const float4 g = sgt[m];
            const float w = fmaxf(fminf(p.z, g.z) - fmaxf(p.x, g.x), 0.0f);
            const float h = fmaxf(fminf(p.w, g.w) - fmaxf(p.y, g.y), 0.0f);
            const float inter = w * h;
            float u = area_p + sarea[m];
            u = u - inter;
            const float d = u + EPSF;            // ref denominator, same op order
            const float thr  = THR * d;
            const float diff = inter - thr;
            const float marg = 1e-6f * thr;
            const bool pos = (d > 0.0f);
            hit   = hit   | (pos & (diff >  marg));
            ambig = ambig | (pos & (fabsf(diff) <= marg));
        }
        if (ambig) {                              // rare: redo exactly (IEEE div)
            hit = false;
            for (int m = 0; m < K; m++) {
                const float4 g = sgt[m];
                const float w = fmaxf(fminf(p.z, g.z) - fmaxf(p.x, g.x), 0.0f);
                const float h = fmaxf(fminf(p.w, g.w) - fmaxf(p.y, g.y), 0.0f);
                const float inter = w * h;
                float u = area_p + sarea[m];
                u = u - inter;
                const float d = u + EPSF;
                hit = hit | ((inter / d) > THR);  // d<0 -> iou<=0 -> false (== ref)
            }
        }

        const float o    = obj[i];
        const bool  mask = (o > 0.0f);
        smask[t] = mask;

        out[i] = mask ? o : (hit ? -1.0f : 0.0f);

        const float2 z = make_float2(0.0f, 0.0f);
        const float2 c = cen[i];
        const float2 s = sca[i];
        const float2 w = wei[i];
        ((float2*)(out + S     ))[i] = mask ? c : z;
        ((float2*)(out + 3 * S ))[i] = mask ? s : z;
        ((float2*)(out + 5 * S ))[i] = mask ? w : z;
    }
    __syncthreads();

    // ---------------- phase 2: class targets + mask (coalesced f4) -------
    const long long base = ((long long)b * N + a0) * C4;
    const float4* cb = cls4 + base;
    float4* tb = (float4*)(out + 7LL  * S) + base;
    float4* mb = (float4*)(out + 87LL * S) + base;

    const int tot = nA * C4;
    for (int idx = t; idx < tot; idx += AB) {
        const bool mask = smask[idx / C4];
        const float4 c = __ldcs(cb + idx);
        float4 tv, mv;
        tv.x = mask ? c.x : -1.0f;  mv.x = (mask & (c.x >= 0.0f)) ? 1.0f : 0.0f;
        tv.y = mask ? c.y : -1.0f;  mv.y = (mask & (c.y >= 0.0f)) ? 1.0f : 0.0f;
        tv.z = mask ? c.z : -1.0f;  mv.z = (mask & (c.z >= 0.0f)) ? 1.0f : 0.0f;
        tv.w = mask ? c.w : -1.0f;  mv.w = (mask & (c.w >= 0.0f)) ? 1.0f : 0.0f;
        __stcs(tb + idx, tv);
        __stcs(mb + idx, mv);
    }
}

extern "C" void kernel_launch(void* const* d_in, const int* in_sizes, int n_in,
                              void* d_out, int out_size)
{
    const float4* bp  = (const float4*)d_in[0];
    const float4* gt  = (const float4*)d_in[1];
    const float*  obj = (const float*) d_in[2];
    const float2* cen = (const float2*)d_in[3];
    const float2* sca = (const float2*)d_in[4];
    const float2* wei = (const float2*)d_in[5];
    const float4* cls = (const float4*)d_in[6];

    const long long S = in_sizes[2];      // b * N
    const int N = (int)(S / BATCH);
    float* out = (float*)d_out;

    dim3 block(AB, 1, 1);
    dim3 grid((N + AB - 1) / AB, BATCH, 1);
    fused_merge_kernel<<<grid, block>>>(bp, gt, obj, cen, sca, wei, cls, out, N, S);
}

// round 5
// speedup vs baseline: 1.4653x; 1.0746x over previous
#include <cuda_runtime.h>

// YOLOV3TargetMerger: b=32, N=22743, M=50, C=80
// Inputs: 0 box_preds[b,N,4] 1 gt_boxes[b,M,4] 2 obj_t[b,N,1]
//         3 centers_t[b,N,2] 4 scales_t[b,N,2] 5 weights_t[b,N,2] 6 clas_t[b,N,80]
// Output (concat f32): obj[S], cen[2S], sca[2S], wei[2S], cls_t[80S], cls_m[80S]

#define BATCH 32
#define MGT   50
#define NCLS  80
#define C4    (NCLS / 4)
#define THR   0.7f
#define EPSF  1e-12f

__global__ void __launch_bounds__(256) merge_main_kernel(
    const float4* __restrict__ bp,
    const float4* __restrict__ gt,
    const float*  __restrict__ obj,
    const float2* __restrict__ cen,
    const float2* __restrict__ sca,
    const float2* __restrict__ wei,
    float* __restrict__ out,
    int N, long long S)
{
    __shared__ float4 sgt[MGT];
    __shared__ float  sarea[MGT];
    __shared__ int    scnt;

    const int b = blockIdx.y;
    const int t = threadIdx.x;

    // compact gt boxes: non-positive width/height => inter==0 vs every anchor,
    // which can never produce a hit (needs d>0, then 0 > 0.7*d is false).
    if (t == 0) scnt = 0;
    __syncthreads();
    if (t < MGT) {
        const float4 g = gt[b * MGT + t];
        if (g.z > g.x && g.w > g.y) {
            const int k = atomicAdd(&scnt, 1);
            sgt[k]   = g;
            sarea[k] = (g.z - g.x) * (g.w - g.y);
        }
    }
    __syncthreads();
    const int K = scnt;                       // ~12.5 expected

    const int n = blockIdx.x * blockDim.x + t;
    if (n >= N) return;
    const long long i = (long long)b * N + n;

    const float4 p = bp[i];
    const float area_p = (p.z - p.x) * (p.w - p.y);

    bool hit = false, ambig = false;
    for (int m = 0; m < K; m++) {
        const float4 g = sgt[m];
        const float w = fmaxf(fminf(p.z, g.z) - fmaxf(p.x, g.x), 0.0f);
        const float h = fmaxf(fminf(p.w, g.w) - fmaxf(p.y, g.y), 0.0f);
        const float inter = w * h;
        float u = area_p + sarea[m];
        u = u - inter;
        const float d = u + EPSF;             // ref denominator, same op order
        const float thr  = THR * d;
        const float diff = inter - thr;
        const float marg = 1e-6f * thr;
        const bool pos = (d > 0.0f);
        hit   = hit   | (pos & (diff >  marg));
        ambig = ambig | (pos & (fabsf(diff) <= marg));
    }
    if (ambig) {                              // rare: redo exactly (IEEE div)
        hit = false;
        for (int m = 0; m < K; m++) {
            const float4 g = sgt[m];
            const float w = fmaxf(fminf(p.z, g.z) - fmaxf(p.x, g.x), 0.0f);
            const float h = fmaxf(fminf(p.w, g.w) - fmaxf(p.y, g.y), 0.0f);
            const float inter = w * h;
            float u = area_p + sarea[m];
            u = u - inter;
            const float d = u + EPSF;
            hit = hit | ((inter / d) > THR);  // d<0 -> iou<=0 -> false (== ref)
        }
    }

    const float o    = obj[i];
    const bool  mask = (o > 0.0f);

    out[i] = mask ? o : (hit ? -1.0f : 0.0f);

    const float2 z = make_float2(0.0f, 0.0f);
    const float2 c = cen[i];
    const float2 s = sca[i];
    const float2 w = wei[i];
    ((float2*)(out + S     ))[i] = mask ? c : z;
    ((float2*)(out + 3 * S ))[i] = mask ? s : z;
    ((float2*)(out + 5 * S ))[i] = mask ? w : z;
}

__global__ void __launch_bounds__(256) merge_class_kernel(
    const float*  __restrict__ obj,
    const float4* __restrict__ cls,
    float4* __restrict__ out_t,
    float4* __restrict__ out_m,
    long long total4)   // = S * C4
{
    const long long idx = (long long)blockIdx.x * blockDim.x + threadIdx.x;
    if (idx >= total4) return;

    const long long anchor = idx / C4;
    const bool mask = (obj[anchor] > 0.0f);   // broadcast in 20-thread groups -> L1/L2

    const float4 c = __ldcs(&cls[idx]);       // streaming: touched once
    float4 t, m;
    t.x = mask ? c.x : -1.0f;  m.x = (mask & (c.x >= 0.0f)) ? 1.0f : 0.0f;
    t.y = mask ? c.y : -1.0f;  m.y = (mask & (c.y >= 0.0f)) ? 1.0f : 0.0f;
    t.z = mask ? c.z : -1.0f;  m.z = (mask & (c.z >= 0.0f)) ? 1.0f : 0.0f;
    t.w = mask ? c.w : -1.0f;  m.w = (mask & (c.w >= 0.0f)) ? 1.0f : 0.0f;

    __stcs(&out_t[idx], t);
    __stcs(&out_m[idx], m);
}

extern "C" void kernel_launch(void* const* d_in, const int* in_sizes, int n_in,
                              void* d_out, int out_size)
{
    const float4* bp  = (const float4*)d_in[0];
    const float4* gt  = (const float4*)d_in[1];
    const float*  obj = (const float*) d_in[2];
    const float2* cen = (const float2*)d_in[3];
    const float2* sca = (const float2*)d_in[4];
    const float2* wei = (const float2*)d_in[5];
    const float*  cls = (const float*) d_in[6];

    const long long S = in_sizes[2];      // b * N
    const int N = (int)(S / BATCH);
    float* out = (float*)d_out;

    {
        dim3 block(256, 1, 1);
        dim3 grid((N + 255) / 256, BATCH, 1);
        merge_main_kernel<<<grid, block>>>(bp, gt, obj, cen, sca, wei, out, N, S);
    }
    {
        const long long total4 = S * C4;
        float4* out_t = (float4*)(out + 7LL  * S);
        float4* out_m = (float4*)(out + 87LL * S);
        const long long blocks = (total4 + 255) / 256;
        merge_class_kernel<<<(unsigned)blocks, 256>>>(obj, (const float4*)cls,
                                                      out_t, out_m, total4);
    }
}

// round 6
// speedup vs baseline: 1.6274x; 1.1106x over previous
#include <cuda_runtime.h>

// YOLOV3TargetMerger: b=32, N=22743, M=50, C=80
// Inputs: 0 box_preds[b,N,4] 1 gt_boxes[b,M,4] 2 obj_t[b,N,1]
//         3 centers_t[b,N,2] 4 scales_t[b,N,2] 5 weights_t[b,N,2] 6 clas_t[b,N,80]
// Output (concat f32): obj[S], cen[2S], sca[2S], wei[2S], cls_t[80S], cls_m[80S]

#define BATCH 32
#define MGT   50
#define NCLS  80
#define C4    (NCLS / 4)
#define THR   0.7f
#define EPSF  1e-12f

__global__ void __launch_bounds__(256) merge_main_kernel(
    const float4* __restrict__ bp,
    const float4* __restrict__ gt,
    const float*  __restrict__ obj,
    const float2* __restrict__ cen,
    const float2* __restrict__ sca,
    const float2* __restrict__ wei,
    float* __restrict__ out,
    int N, long long S)
{
    __shared__ float4 sgt[MGT];
    __shared__ float  sarea[MGT];
    __shared__ int    scnt;

    const int b = blockIdx.y;
    const int t = threadIdx.x;

    // compact gt boxes: non-positive width/height => inter==0 vs every anchor,
    // which can never produce a hit (needs d>0, then 0 > 0.7*d is false).
    if (t == 0) scnt = 0;
    __syncthreads();
    if (t < MGT) {
        const float4 g = gt[b * MGT + t];
        if (g.z > g.x && g.w > g.y) {
            const int k = atomicAdd(&scnt, 1);
            sgt[k]   = g;
            sarea[k] = (g.z - g.x) * (g.w - g.y);
        }
    }
    __syncthreads();
    const int K = scnt;                       // ~12.5 expected

    const int n = blockIdx.x * blockDim.x + t;
    if (n >= N) return;
    const long long i = (long long)b * N + n;

    const float o    = obj[i];
    const bool  mask = (o > 0.0f);

    float objout;
    if (mask) {
        objout = o;                           // IOU result unused -> skip loop
    } else {
        const float4 p = bp[i];
        const float area_p = (p.z - p.x) * (p.w - p.y);

        bool hit = false, ambig = false;
        for (int m = 0; m < K; m++) {
            const float4 g = sgt[m];
            const float w = fmaxf(fminf(p.z, g.z) - fmaxf(p.x, g.x), 0.0f);
            const float h = fmaxf(fminf(p.w, g.w) - fmaxf(p.y, g.y), 0.0f);
            const float inter = w * h;
            float u = area_p + sarea[m];
            u = u - inter;
            const float d = u + EPSF;         // ref denominator, same op order
            const float thr  = THR * d;
            const float diff = inter - thr;
            const float marg = 1e-6f * thr;
            const bool pos = (d > 0.0f);
            hit   = hit   | (pos & (diff >  marg));
            ambig = ambig | (pos & (fabsf(diff) <= marg));
        }
        if (ambig) {                          // rare: redo exactly (IEEE div)
            hit = false;
            for (int m = 0; m < K; m++) {
                const float4 g = sgt[m];
                const float w = fmaxf(fminf(p.z, g.z) - fmaxf(p.x, g.x), 0.0f);
                const float h = fmaxf(fminf(p.w, g.w) - fmaxf(p.y, g.y), 0.0f);
                const float inter = w * h;
                float u = area_p + sarea[m];
                u = u - inter;
                const float d = u + EPSF;
                hit = hit | ((inter / d) > THR);  // d<0 -> iou<=0 -> false (== ref)
            }
        }
        objout = hit ? -1.0f : 0.0f;
    }

    out[i] = objout;

    float2 c, s, w;
    if (mask) {
        c = cen[i]; s = sca[i]; w = wei[i];   // only read when used
    } else {
        c = s = w = make_float2(0.0f, 0.0f);
    }
    ((float2*)(out + S     ))[i] = c;
    ((float2*)(out + 3 * S ))[i] = s;
    ((float2*)(out + 5 * S ))[i] = w;
}

__global__ void __launch_bounds__(256) merge_class_kernel(
    const float*  __restrict__ obj,
    const float4* __restrict__ cls,
    float4* __restrict__ out_t,
    float4* __restrict__ out_m,
    long long total4)   // = S * C4
{
    const long long idx = (long long)blockIdx.x * blockDim.x + threadIdx.x;
    if (idx >= total4) return;

    const long long anchor = idx / C4;
    const bool mask = (obj[anchor] > 0.0f);   // uniform over each anchor's 20 lanes

    float4 t, m;
    if (mask) {
        const float4 c = __ldcs(&cls[idx]);   // only ~50% of anchors read cls
        t = c;
        m.x = (c.x >= 0.0f) ? 1.0f : 0.0f;
        m.y = (c.y >= 0.0f) ? 1.0f : 0.0f;
        m.z = (c.z >= 0.0f) ? 1.0f : 0.0f;
        m.w = (c.w >= 0.0f) ? 1.0f : 0.0f;
    } else {
        t = make_float4(-1.0f, -1.0f, -1.0f, -1.0f);
        m = make_float4(0.0f, 0.0f, 0.0f, 0.0f);
    }

    __stcs(&out_t[idx], t);
    __stcs(&out_m[idx], m);
}

extern "C" void kernel_launch(void* const* d_in, const int* in_sizes, int n_in,
                              void* d_out, int out_size)
{
    const float4* bp  = (const float4*)d_in[0];
    const float4* gt  = (const float4*)d_in[1];
    const float*  obj = (const float*) d_in[2];
    const float2* cen = (const float2*)d_in[3];
    const float2* sca = (const float2*)d_in[4];
    const float2* wei = (const float2*)d_in[5];
    const float*  cls = (const float*) d_in[6];

    const long long S = in_sizes[2];      // b * N
    const int N = (int)(S / BATCH);
    float* out = (float*)d_out;

    {
        dim3 block(256, 1, 1);
        dim3 grid((N + 255) / 256, BATCH, 1);
        merge_main_kernel<<<grid, block>>>(bp, gt, obj, cen, sca, wei, out, N, S);
    }
    {
        const long long total4 = S * C4;
        float4* out_t = (float4*)(out + 7LL  * S);
        float4* out_m = (float4*)(out + 87LL * S);
        const long long blocks = (total4 + 255) / 256;
        merge_class_kernel<<<(unsigned)blocks, 256>>>(obj, (const float4*)cls,
                                                      out_t, out_m, total4);
    }
}